// round 15
// baseline (speedup 1.0000x reference)
#include <cuda_runtime.h>
#include <cuda_bf16.h>
#include <math.h>
#include <stdint.h>

#define B_  64
#define T_  256
#define H_  1024
#define G4  4096
#define NBLK 128

#define KCAT 3072      // split-K: [hi | lo | hi] x [hi | hi | lo]
#define NCH  48        // KCAT / 64

// ---- scratch (device globals) ----
__device__ float g_gx[(size_t)T_ * B_ * G4];
__device__ __nv_bfloat16 g_acat[(size_t)16384 * KCAT];
__device__ __nv_bfloat16 g_hcat[(size_t)16384 * KCAT];   // written by recurrence epilogue
__device__ __nv_bfloat16 g_h0cat[64 * 2048];             // h0 split [row][hi 1024 | lo 1024]
__device__ __nv_bfloat16 g_bgx[(size_t)4096 * KCAT];
__device__ __nv_bfloat16 g_bwy[(size_t)1024 * KCAT];
__device__ float g_bcat[4096];

// two-level barrier state
__device__ unsigned g_cnt_grp[8];    // 16 blocks per group
__device__ unsigned g_cnt_master = 0;
__device__ unsigned g_bar_gen    = 0;

__device__ __forceinline__ float sigf(float x)    { return 1.f / (1.f + __expf(-x)); }
__device__ __forceinline__ float tanhfast(float x){ return 2.f * sigf(2.f * x) - 1.f; }

// ============================================================
// base-target PTX helpers
// ============================================================
__device__ __forceinline__ uint32_t smem_u32(const void* p) {
    uint32_t a;
    asm("{ .reg .u64 t; cvta.to.shared.u64 t, %1; cvt.u32.u64 %0, t; }" : "=r"(a) : "l"(p));
    return a;
}
#define SWZ128(o) ((o) ^ (((o) >> 3) & 0x70))

__device__ __forceinline__ void cpasync16(uint32_t dst, const void* src) {
    asm volatile("cp.async.cg.shared.global [%0], [%1], 16;" :: "r"(dst), "l"(src));
}
#define CP_COMMIT() asm volatile("cp.async.commit_group;" ::: "memory")
#define CP_WAIT0()  asm volatile("cp.async.wait_group 0;" ::: "memory")
#define CP_WAIT1()  asm volatile("cp.async.wait_group 1;" ::: "memory")

__device__ __forceinline__ void ldsm4(uint32_t* r, uint32_t addr) {
    asm volatile("ldmatrix.sync.aligned.m8n8.x4.shared.b16 {%0,%1,%2,%3}, [%4];"
                 : "=r"(r[0]), "=r"(r[1]), "=r"(r[2]), "=r"(r[3]) : "r"(addr));
}
__device__ __forceinline__ void mma16816(float* d, const uint32_t* a, const uint32_t* b) {
    asm volatile(
        "mma.sync.aligned.m16n8k16.row.col.f32.bf16.bf16.f32 "
        "{%0,%1,%2,%3}, {%4,%5,%6,%7}, {%8,%9}, {%0,%1,%2,%3};"
        : "+f"(d[0]), "+f"(d[1]), "+f"(d[2]), "+f"(d[3])
        : "r"(a[0]), "r"(a[1]), "r"(a[2]), "r"(a[3]), "r"(b[0]), "r"(b[1]));
}
__device__ __forceinline__ void split_bf(float x, __nv_bfloat16& h, __nv_bfloat16& l) {
    h = __float2bfloat16(x);
    l = __float2bfloat16(x - __bfloat162float(h));
}

// ============================================================
// mma.sync bf16-split GEMM v2: CTA tile 128m x 256n, 256 threads,
// 8 warps of 64x64, 2-buffer cp.async (48 KB/buf -> 96 KB smem).
// Halves A L2 traffic vs 128x128; B stays L2-resident.
// ============================================================
template<bool REMAP>
__global__ void __launch_bounds__(256, 1) gemm_mma2(
    const __nv_bfloat16* __restrict__ A, const __nv_bfloat16* __restrict__ Bm,
    const float* __restrict__ bias, float* __restrict__ C, int ldc)
{
    extern __shared__ char sm[];
    const uint32_t sb = smem_u32(sm);
    const int tid = threadIdx.x;
    const int wid = tid >> 5;
    const int lane = tid & 31;
    const int m0 = blockIdx.y * 128;
    const int n0 = blockIdx.x * 256;
    const int wm = (wid & 1) * 64;       // 2 m-warps
    const int wn = (wid >> 1) * 64;      // 4 n-warps

    const __nv_bfloat16* Ab = A + (size_t)m0 * KCAT;
    const __nv_bfloat16* Bb = Bm + (size_t)n0 * KCAT;

    const int l_row = tid >> 3;          // 0..31
    const int l_c16 = tid & 7;
    auto issue = [&](int buf, int kbase) {
        uint32_t ab = sb + buf * 49152;
        uint32_t bbs = ab + 16384;
        #pragma unroll
        for (int i = 0; i < 4; i++) {            // A: 128 rows
            int row = l_row + i * 32;
            cpasync16(ab + SWZ128(row * 128 + l_c16 * 16),
                      Ab + (size_t)row * KCAT + kbase + l_c16 * 8);
        }
        #pragma unroll
        for (int i = 0; i < 8; i++) {            // B: 256 rows
            int row = l_row + i * 32;
            cpasync16(bbs + SWZ128(row * 128 + l_c16 * 16),
                      Bb + (size_t)row * KCAT + kbase + l_c16 * 8);
        }
        CP_COMMIT();
    };

    float acc[4][8][4];
    #pragma unroll
    for (int i = 0; i < 4; i++)
        #pragma unroll
        for (int j = 0; j < 8; j++)
            #pragma unroll
            for (int q = 0; q < 4; q++) acc[i][j][q] = 0.f;

    const int a_row = wm + (lane & 15);
    const int a_kb  = (lane >> 4) * 16;
    const int b_rowb = wn + ((lane >> 4) << 3) + (lane & 7);
    const int b_kb  = ((lane >> 3) & 1) * 16;

    issue(0, 0);

    for (int c = 0; c < NCH; c++) {
        if (c + 1 < NCH) { issue((c + 1) & 1, (c + 1) * 64); CP_WAIT1(); }
        else             { CP_WAIT0(); }
        __syncthreads();

        uint32_t ab = sb + (c & 1) * 49152;
        uint32_t bbs = ab + 16384;
        #pragma unroll
        for (int ks = 0; ks < 4; ks++) {
            uint32_t afr[4][4], bfr[4][4];
            #pragma unroll
            for (int mt = 0; mt < 4; mt++)
                ldsm4(afr[mt], ab + SWZ128((a_row + mt * 16) * 128 + ks * 32 + a_kb));
            #pragma unroll
            for (int ng = 0; ng < 4; ng++)
                ldsm4(bfr[ng], bbs + SWZ128((b_rowb + ng * 16) * 128 + ks * 32 + b_kb));
            #pragma unroll
            for (int mt = 0; mt < 4; mt++)
                #pragma unroll
                for (int ng = 0; ng < 4; ng++) {
                    mma16816(acc[mt][2 * ng],     afr[mt], &bfr[ng][0]);
                    mma16816(acc[mt][2 * ng + 1], afr[mt], &bfr[ng][2]);
                }
        }
        __syncthreads();
    }

    const int er = lane >> 2;
    const int ec = (lane & 3) * 2;
    #pragma unroll
    for (int mt = 0; mt < 4; mt++) {
        int r_lo = m0 + wm + mt * 16 + er;
        int r_hi = r_lo + 8;
        size_t off_lo, off_hi;
        if (REMAP) {
            off_lo = ((size_t)(r_lo & 255) * 64 + (r_lo >> 8)) * (size_t)ldc;
            off_hi = ((size_t)(r_hi & 255) * 64 + (r_hi >> 8)) * (size_t)ldc;
        } else {
            off_lo = (size_t)r_lo * (size_t)ldc;
            off_hi = (size_t)r_hi * (size_t)ldc;
        }
        #pragma unroll
        for (int nt = 0; nt < 8; nt++) {
            int col = n0 + wn + nt * 8 + ec;
            float b0 = bias[col], b1 = bias[col + 1];
            *(float2*)(C + off_lo + col) = make_float2(acc[mt][nt][0] + b0, acc[mt][nt][1] + b1);
            *(float2*)(C + off_hi + col) = make_float2(acc[mt][nt][2] + b0, acc[mt][nt][3] + b1);
        }
    }
}

// ============================================================
// prep kernels (exact R9-bench versions)
// ============================================================
__global__ void __launch_bounds__(256) prep_split(
    const float* __restrict__ src, __nv_bfloat16* __restrict__ dst)
{
    int t = blockIdx.x * 256 + threadIdx.x;
    int r = t >> 8, q = t & 255;
    float4 v = *(const float4*)(src + (size_t)r * 1024 + q * 4);
    __nv_bfloat16 h[4], l[4];
    split_bf(v.x, h[0], l[0]); split_bf(v.y, h[1], l[1]);
    split_bf(v.z, h[2], l[2]); split_bf(v.w, h[3], l[3]);
    __nv_bfloat16* d = dst + (size_t)r * KCAT;
    __nv_bfloat162 hp0 = {h[0], h[1]}, hp1 = {h[2], h[3]};
    __nv_bfloat162 lp0 = {l[0], l[1]}, lp1 = {l[2], l[3]};
    *(__nv_bfloat162*)(d + q * 4)         = hp0;
    *(__nv_bfloat162*)(d + q * 4 + 2)     = hp1;
    *(__nv_bfloat162*)(d + 1024 + q * 4)     = lp0;
    *(__nv_bfloat162*)(d + 1024 + q * 4 + 2) = lp1;
    *(__nv_bfloat162*)(d + 2048 + q * 4)     = hp0;
    *(__nv_bfloat162*)(d + 2048 + q * 4 + 2) = hp1;
}

__global__ void __launch_bounds__(256) prep_wsplit(
    const float* __restrict__ W0, const float* __restrict__ W1,
    const float* __restrict__ W2, const float* __restrict__ W3,
    __nv_bfloat16* __restrict__ dst)
{
    int t = blockIdx.x * 256 + threadIdx.x;
    int n = t / 768;
    int k4 = (t - n * 768) * 4;
    int band = k4 >> 10;
    int kk = k4 & 1023;
    int g = n >> 10, c = n & 1023;
    const float* W = (g == 0) ? W0 : (g == 1) ? W1 : (g == 2) ? W2 : W3;
    __nv_bfloat16 o[4];
    #pragma unroll
    for (int j = 0; j < 4; j++) {
        float w = __ldg(W + (size_t)(kk + j) * 1024 + c);
        __nv_bfloat16 h, l;
        split_bf(w, h, l);
        o[j] = (band < 2) ? h : l;
    }
    __nv_bfloat16* d = dst + (size_t)n * KCAT + k4;
    *(__nv_bfloat162*)(d)     = {o[0], o[1]};
    *(__nv_bfloat162*)(d + 2) = {o[2], o[3]};
}

__global__ void __launch_bounds__(256) prep_bias(
    const float* __restrict__ b0, const float* __restrict__ b1,
    const float* __restrict__ b2, const float* __restrict__ b3)
{
    int n = blockIdx.x * 256 + threadIdx.x;
    int g = n >> 10, c = n & 1023;
    const float* b = (g == 0) ? b0 : (g == 1) ? b1 : (g == 2) ? b2 : b3;
    g_bcat[n] = b[c];
}

__global__ void __launch_bounds__(256) prep_h0(const float* __restrict__ h0)
{
    int row = blockIdx.x;
    #pragma unroll
    for (int i = 0; i < 4; i++) {
        int k = i * 256 + threadIdx.x;
        float v = h0[row * 1024 + k];
        __nv_bfloat16 hi, lo;
        split_bf(v, hi, lo);
        g_h0cat[row * 2048 + k]        = hi;
        g_h0cat[row * 2048 + 1024 + k] = lo;
    }
}

// ============================================================
// two-level grid barrier (R14 version)
// ============================================================
__device__ __forceinline__ void grid_sync_2lvl(int tid, int bid)
{
    __syncthreads();
    if (tid == 0) {
        unsigned gen = *(volatile unsigned*)&g_bar_gen;
        __threadfence();
        if (atomicAdd(&g_cnt_grp[bid & 7], 1u) == 15u) {
            g_cnt_grp[bid & 7] = 0;
            __threadfence();
            if (atomicAdd(&g_cnt_master, 1u) == 7u) {
                g_cnt_master = 0;
                __threadfence();
                atomicExch(&g_bar_gen, gen + 1u);
            }
        }
        while (*(volatile unsigned*)&g_bar_gen == gen) { __nanosleep(32); }
        __threadfence();
    }
    __syncthreads();
}

// ============================================================
// Tensorized persistent LSTM recurrence (exact R14 version)
// ============================================================
#define RSM_ULO 65536
#define RSM_H   131072
#define RSM_HBUF 32768
#define RSM_TOTAL 196608

extern "C" __global__ void __launch_bounds__(256, 1) lstm_mma(
    const float* __restrict__ Ui, const float* __restrict__ Uf,
    const float* __restrict__ Uj, const float* __restrict__ Uo,
    const float* __restrict__ c0)
{
    extern __shared__ char sm[];
    const uint32_t sb = smem_u32(sm);
    const int tid  = threadIdx.x;
    const int lane = tid & 31;
    const int w    = tid >> 5;
    const int wm   = (w & 3) * 16;
    const int gh   = w >> 2;
    const int n0   = blockIdx.x * 8;

    const float* Uptr[4] = {Ui, Uf, Uj, Uo};
    for (int it = 0; it < 128; it++) {
        int idx = it * 256 + tid;
        int k = idx >> 5, nrow = idx & 31;
        int g = nrow >> 3, c = nrow & 7;
        float v = __ldg(Uptr[g] + (size_t)k * 1024 + n0 + c);
        __nv_bfloat16 hi, lo;
        split_bf(v, hi, lo);
        uint32_t off = (k >> 6) * 4096 + SWZ128(nrow * 128 + (k & 63) * 2);
        *(__nv_bfloat16*)(sm + off)           = hi;
        *(__nv_bfloat16*)(sm + RSM_ULO + off) = lo;
    }

    const int e_row = tid >> 2;
    const int e_c2  = (tid & 3) * 2;
    float2 creg = *(const float2*)(c0 + e_row * H_ + n0 + e_c2);
    __syncthreads();

    const int a_row = wm + (lane & 15);
    const int a_kb  = (lane >> 4) * 16;
    const int b_row = gh * 16 + ((lane >> 4) << 3) + (lane & 7);
    const int b_kb  = ((lane >> 3) & 1) * 16;
    const int er = lane >> 2;
    const int ec = (lane & 3) * 2;

    float* sgf = (float*)(sm + RSM_H);

    const float* gx_cell = g_gx + (size_t)e_row * G4 + n0 + e_c2;
    float2 gxi = *(const float2*)(gx_cell);
    float2 gxf = *(const float2*)(gx_cell + 1024);
    float2 gxj = *(const float2*)(gx_cell + 2048);
    float2 gxo = *(const float2*)(gx_cell + 3072);

    for (int t = 0; t < T_; t++) {
        const __nv_bfloat16* hbase;
        size_t rstr;
        if (t == 0) { hbase = g_h0cat;                         rstr = 2048; }
        else        { hbase = g_hcat + (size_t)(t - 1) * KCAT; rstr = 256 * (size_t)KCAT; }

        auto issue = [&](int bf, int cc) {
            uint32_t hb = sb + RSM_H + bf * RSM_HBUF;
            int kbase = cc * 128;
            #pragma unroll
            for (int i = 0; i < 8; i++) {
                int u = i * 256 + tid;
                int half = u >> 10, rem = u & 1023;
                int r = rem >> 4, seg = rem & 15;
                const __nv_bfloat16* src =
                    hbase + (size_t)r * rstr + half * 1024 + kbase + seg * 8;
                uint32_t dst = hb + half * 16384 + (seg >> 3) * 8192
                             + SWZ128(r * 128 + (seg & 7) * 16);
                cpasync16(dst, src);
            }
            CP_COMMIT();
        };

        float acc[2][4];
        #pragma unroll
        for (int i = 0; i < 2; i++)
            #pragma unroll
            for (int q = 0; q < 4; q++) acc[i][q] = 0.f;

        issue(0, 0);

        for (int cc = 0; cc < 8; cc++) {
            if (cc < 7) { issue((cc + 1) & 1, cc + 1); CP_WAIT1(); }
            else        { CP_WAIT0(); }
            __syncthreads();

            uint32_t hb = sb + RSM_H + (cc & 1) * RSM_HBUF;
            #pragma unroll
            for (int ks = 0; ks < 8; ks++) {
                int sub = ks >> 2, ks4 = ks & 3;
                uint32_t a_off = sub * 8192 + SWZ128(a_row * 128 + ks4 * 32 + a_kb);
                uint32_t ahi[4], alo[4], bhi[4], blo[4];
                ldsm4(ahi, hb + a_off);
                ldsm4(alo, hb + 16384 + a_off);
                uint32_t b_off = (cc * 2 + sub) * 4096
                               + SWZ128(b_row * 128 + ks4 * 32 + b_kb);
                ldsm4(bhi, sb + b_off);
                ldsm4(blo, sb + RSM_ULO + b_off);
                mma16816(acc[0], ahi, &bhi[0]);
                mma16816(acc[1], ahi, &bhi[2]);
                mma16816(acc[0], alo, &bhi[0]);
                mma16816(acc[1], alo, &bhi[2]);
                mma16816(acc[0], ahi, &blo[0]);
                mma16816(acc[1], ahi, &blo[2]);
            }
            __syncthreads();
        }

        #pragma unroll
        for (int nt = 0; nt < 2; nt++) {
            int g = gh * 2 + nt;
            sgf[(wm + er) * 34 + g * 8 + ec]         = acc[nt][0];
            sgf[(wm + er) * 34 + g * 8 + ec + 1]     = acc[nt][1];
            sgf[(wm + er + 8) * 34 + g * 8 + ec]     = acc[nt][2];
            sgf[(wm + er + 8) * 34 + g * 8 + ec + 1] = acc[nt][3];
        }
        __syncthreads();

        float2 pg[4];
        #pragma unroll
        for (int g = 0; g < 4; g++)
            pg[g] = *(const float2*)&sgf[e_row * 34 + g * 8 + e_c2];

        float2 hv;
        {
            float gi = pg[0].x + gxi.x, gf = pg[1].x + gxf.x;
            float gj = pg[2].x + gxj.x, go = pg[3].x + gxo.x;
            float iv = sigf(gi), fv = sigf(gf), jv = tanhfast(gj), ov = sigf(go);
            creg.x = fv * creg.x + iv * jv;
            hv.x = ov * tanhfast(creg.x);
        }
        {
            float gi = pg[0].y + gxi.y, gf = pg[1].y + gxf.y;
            float gj = pg[2].y + gxj.y, go = pg[3].y + gxo.y;
            float iv = sigf(gi), fv = sigf(gf), jv = tanhfast(gj), ov = sigf(go);
            creg.y = fv * creg.y + iv * jv;
            hv.y = ov * tanhfast(creg.y);
        }

        {
            __nv_bfloat16 hx, lx, hy, ly;
            split_bf(hv.x, hx, lx);
            split_bf(hv.y, hy, ly);
            __nv_bfloat16* d = g_hcat + ((size_t)e_row * 256 + t) * KCAT + n0 + e_c2;
            __nv_bfloat162 hp = {hx, hy}, lp = {lx, ly};
            *(__nv_bfloat162*)(d)        = hp;
            *(__nv_bfloat162*)(d + 1024) = lp;
            *(__nv_bfloat162*)(d + 2048) = hp;
        }

        if (t + 1 < T_) {
            const float* p = gx_cell + (size_t)(t + 1) * 64 * G4;
            gxi = *(const float2*)(p);
            gxf = *(const float2*)(p + 1024);
            gxj = *(const float2*)(p + 2048);
            gxo = *(const float2*)(p + 3072);
        }

        grid_sync_2lvl(tid, blockIdx.x);
    }
}

// ============================================================
// Inputs: x, h0, c0, W_i..W_o, U_i..U_o, b_i..b_o, W_y, b_y
// ============================================================
extern "C" void kernel_launch(void* const* d_in, const int* in_sizes, int n_in,
                              void* d_out, int out_size)
{
    const float* x  = (const float*)d_in[0];
    const float* h0 = (const float*)d_in[1];
    const float* c0 = (const float*)d_in[2];
    const float* W[4] = {(const float*)d_in[3], (const float*)d_in[4],
                         (const float*)d_in[5], (const float*)d_in[6]};
    const float* U[4] = {(const float*)d_in[7], (const float*)d_in[8],
                         (const float*)d_in[9], (const float*)d_in[10]};
    const float* bb[4] = {(const float*)d_in[11], (const float*)d_in[12],
                          (const float*)d_in[13], (const float*)d_in[14]};
    const float* Wy = (const float*)d_in[15];
    const float* by = (const float*)d_in[16];
    float* y = (float*)d_out;

    float* gx_ptr; cudaGetSymbolAddress((void**)&gx_ptr, g_gx);
    __nv_bfloat16* acat; cudaGetSymbolAddress((void**)&acat, g_acat);
    __nv_bfloat16* hcat; cudaGetSymbolAddress((void**)&hcat, g_hcat);
    __nv_bfloat16* bgx;  cudaGetSymbolAddress((void**)&bgx,  g_bgx);
    __nv_bfloat16* bwy;  cudaGetSymbolAddress((void**)&bwy,  g_bwy);
    float* bcat; cudaGetSymbolAddress((void**)&bcat, g_bcat);

    const int gemm_smem = 2 * 49152;   // 96 KB
    cudaFuncSetAttribute(gemm_mma2<true>,
                         cudaFuncAttributeMaxDynamicSharedMemorySize, gemm_smem);
    cudaFuncSetAttribute(gemm_mma2<false>,
                         cudaFuncAttributeMaxDynamicSharedMemorySize, gemm_smem);
    cudaFuncSetAttribute(lstm_mma,
                         cudaFuncAttributeMaxDynamicSharedMemorySize, RSM_TOTAL);

    // prep
    prep_split<<<16384, 256>>>(x, acat);
    prep_wsplit<<<12288, 256>>>(W[0], W[1], W[2], W[3], bgx);
    prep_wsplit<<<3072, 256>>>(Wy, Wy, Wy, Wy, bwy);
    prep_bias<<<16, 256>>>(bb[0], bb[1], bb[2], bb[3]);
    prep_h0<<<64, 256>>>(h0);

    // gx = x @ [W_i|W_f|W_j|W_o] + b  (REMAP into [T][B][4H])
    gemm_mma2<true><<<dim3(G4 / 256, 16384 / 128), 256, gemm_smem>>>(
        acat, bgx, bcat, gx_ptr, G4);

    // tensorized persistent recurrence (writes g_hcat directly)
    lstm_mma<<<NBLK, 256, RSM_TOTAL>>>(U[0], U[1], U[2], U[3], c0);

    // y = hs @ W_y + b_y
    gemm_mma2<false><<<dim3(1024 / 256, 16384 / 128), 256, gemm_smem>>>(
        hcat, bwy, by, y, 1024);
}

// round 16
// speedup vs baseline: 1.1094x; 1.1094x over previous
#include <cuda_runtime.h>
#include <cuda_bf16.h>
#include <math.h>
#include <stdint.h>

#define B_  64
#define T_  256
#define H_  1024
#define G4  4096
#define NBLK 128

#define KCAT 3072      // split-K: [hi | lo | hi] x [hi | hi | lo]
#define NCH  48        // KCAT / 64

// ---- scratch (device globals) ----
__device__ float g_gx[(size_t)T_ * B_ * G4];
__device__ __nv_bfloat16 g_acat[(size_t)16384 * KCAT];
__device__ __nv_bfloat16 g_hcat[(size_t)16384 * KCAT];   // written by recurrence epilogue
__device__ __nv_bfloat16 g_h0cat[64 * 2048];             // h0 split [row][hi 1024 | lo 1024]
__device__ __nv_bfloat16 g_bgx[(size_t)4096 * KCAT];
__device__ __nv_bfloat16 g_bwy[(size_t)1024 * KCAT];
__device__ float g_bcat[4096];

__device__ unsigned g_bar_count = 0;
__device__ unsigned g_bar_gen   = 0;

__device__ __forceinline__ float sigf(float x)    { return 1.f / (1.f + __expf(-x)); }
__device__ __forceinline__ float tanhfast(float x){ return 2.f * sigf(2.f * x) - 1.f; }

// ============================================================
// base-target PTX helpers
// ============================================================
__device__ __forceinline__ uint32_t smem_u32(const void* p) {
    uint32_t a;
    asm("{ .reg .u64 t; cvta.to.shared.u64 t, %1; cvt.u32.u64 %0, t; }" : "=r"(a) : "l"(p));
    return a;
}
#define SWZ128(o) ((o) ^ (((o) >> 3) & 0x70))

__device__ __forceinline__ void cpasync16(uint32_t dst, const void* src) {
    asm volatile("cp.async.cg.shared.global [%0], [%1], 16;" :: "r"(dst), "l"(src));
}
#define CP_COMMIT() asm volatile("cp.async.commit_group;" ::: "memory")
#define CP_WAIT0()  asm volatile("cp.async.wait_group 0;" ::: "memory")
#define CP_WAIT1()  asm volatile("cp.async.wait_group 1;" ::: "memory")

__device__ __forceinline__ void ldsm4(uint32_t* r, uint32_t addr) {
    asm volatile("ldmatrix.sync.aligned.m8n8.x4.shared.b16 {%0,%1,%2,%3}, [%4];"
                 : "=r"(r[0]), "=r"(r[1]), "=r"(r[2]), "=r"(r[3]) : "r"(addr));
}
__device__ __forceinline__ void mma16816(float* d, const uint32_t* a, const uint32_t* b) {
    asm volatile(
        "mma.sync.aligned.m16n8k16.row.col.f32.bf16.bf16.f32 "
        "{%0,%1,%2,%3}, {%4,%5,%6,%7}, {%8,%9}, {%0,%1,%2,%3};"
        : "+f"(d[0]), "+f"(d[1]), "+f"(d[2]), "+f"(d[3])
        : "r"(a[0]), "r"(a[1]), "r"(a[2]), "r"(a[3]), "r"(b[0]), "r"(b[1]));
}
__device__ __forceinline__ void split_bf(float x, __nv_bfloat16& h, __nv_bfloat16& l) {
    h = __float2bfloat16(x);
    l = __float2bfloat16(x - __bfloat162float(h));
}

// ============================================================
// mma.sync bf16-split GEMM (128x128 tile, 2-buffer cp.async, occ 2)
// ============================================================
template<bool REMAP>
__global__ void __launch_bounds__(256, 2) gemm_mma(
    const __nv_bfloat16* __restrict__ A, const __nv_bfloat16* __restrict__ Bm,
    const float* __restrict__ bias, float* __restrict__ C, int ldc)
{
    extern __shared__ char sm[];
    const uint32_t sb = smem_u32(sm);
    const int tid = threadIdx.x;
    const int wid = tid >> 5;
    const int lane = tid & 31;
    const int m0 = blockIdx.y * 128;
    const int n0 = blockIdx.x * 128;
    const int wm = (wid & 1) * 64;
    const int wn = (wid >> 1) * 32;

    const __nv_bfloat16* Ab = A + (size_t)m0 * KCAT;
    const __nv_bfloat16* Bb = Bm + (size_t)n0 * KCAT;

    const int l_row = tid >> 3;
    const int l_c16 = tid & 7;
    auto issue = [&](int buf, int kbase) {
        uint32_t ab = sb + buf * 32768;
        uint32_t bbs = ab + 16384;
        #pragma unroll
        for (int i = 0; i < 4; i++) {
            int row = l_row + i * 32;
            cpasync16(ab + SWZ128(row * 128 + l_c16 * 16),
                      Ab + (size_t)row * KCAT + kbase + l_c16 * 8);
        }
        #pragma unroll
        for (int i = 0; i < 4; i++) {
            int row = l_row + i * 32;
            cpasync16(bbs + SWZ128(row * 128 + l_c16 * 16),
                      Bb + (size_t)row * KCAT + kbase + l_c16 * 8);
        }
        CP_COMMIT();
    };

    float acc[4][4][4];
    #pragma unroll
    for (int i = 0; i < 4; i++)
        #pragma unroll
        for (int j = 0; j < 4; j++)
            #pragma unroll
            for (int q = 0; q < 4; q++) acc[i][j][q] = 0.f;

    const int a_row = wm + (lane & 15);
    const int a_kb  = (lane >> 4) * 16;
    const int b_row = wn + ((lane >> 4) << 3) + (lane & 7);
    const int b_kb  = ((lane >> 3) & 1) * 16;

    issue(0, 0);

    for (int c = 0; c < NCH; c++) {
        if (c + 1 < NCH) { issue((c + 1) & 1, (c + 1) * 64); CP_WAIT1(); }
        else             { CP_WAIT0(); }
        __syncthreads();

        uint32_t ab = sb + (c & 1) * 32768;
        uint32_t bbs = ab + 16384;
        #pragma unroll
        for (int ks = 0; ks < 4; ks++) {
            uint32_t afr[4][4], bfr[2][4];
            #pragma unroll
            for (int mt = 0; mt < 4; mt++)
                ldsm4(afr[mt], ab + SWZ128((a_row + mt * 16) * 128 + ks * 32 + a_kb));
            #pragma unroll
            for (int np = 0; np < 2; np++)
                ldsm4(bfr[np], bbs + SWZ128((b_row + np * 16) * 128 + ks * 32 + b_kb));
            #pragma unroll
            for (int mt = 0; mt < 4; mt++) {
                mma16816(acc[mt][0], afr[mt], &bfr[0][0]);
                mma16816(acc[mt][1], afr[mt], &bfr[0][2]);
                mma16816(acc[mt][2], afr[mt], &bfr[1][0]);
                mma16816(acc[mt][3], afr[mt], &bfr[1][2]);
            }
        }
        __syncthreads();
    }

    const int er = lane >> 2;
    const int ec = (lane & 3) * 2;
    #pragma unroll
    for (int mt = 0; mt < 4; mt++) {
        int r_lo = m0 + wm + mt * 16 + er;
        int r_hi = r_lo + 8;
        size_t off_lo, off_hi;
        if (REMAP) {
            off_lo = ((size_t)(r_lo & 255) * 64 + (r_lo >> 8)) * (size_t)ldc;
            off_hi = ((size_t)(r_hi & 255) * 64 + (r_hi >> 8)) * (size_t)ldc;
        } else {
            off_lo = (size_t)r_lo * (size_t)ldc;
            off_hi = (size_t)r_hi * (size_t)ldc;
        }
        #pragma unroll
        for (int nt = 0; nt < 4; nt++) {
            int col = n0 + wn + nt * 8 + ec;
            float b0 = bias[col], b1 = bias[col + 1];
            *(float2*)(C + off_lo + col) = make_float2(acc[mt][nt][0] + b0, acc[mt][nt][1] + b1);
            *(float2*)(C + off_hi + col) = make_float2(acc[mt][nt][2] + b0, acc[mt][nt][3] + b1);
        }
    }
}

// ============================================================
// prep kernels
// ============================================================
__global__ void __launch_bounds__(256) prep_split(
    const float* __restrict__ src, __nv_bfloat16* __restrict__ dst)
{
    int t = blockIdx.x * 256 + threadIdx.x;
    int r = t >> 8, q = t & 255;
    float4 v = *(const float4*)(src + (size_t)r * 1024 + q * 4);
    __nv_bfloat16 h[4], l[4];
    split_bf(v.x, h[0], l[0]); split_bf(v.y, h[1], l[1]);
    split_bf(v.z, h[2], l[2]); split_bf(v.w, h[3], l[3]);
    __nv_bfloat16* d = dst + (size_t)r * KCAT;
    __nv_bfloat162 hp0 = {h[0], h[1]}, hp1 = {h[2], h[3]};
    __nv_bfloat162 lp0 = {l[0], l[1]}, lp1 = {l[2], l[3]};
    *(__nv_bfloat162*)(d + q * 4)         = hp0;
    *(__nv_bfloat162*)(d + q * 4 + 2)     = hp1;
    *(__nv_bfloat162*)(d + 1024 + q * 4)     = lp0;
    *(__nv_bfloat162*)(d + 1024 + q * 4 + 2) = lp1;
    *(__nv_bfloat162*)(d + 2048 + q * 4)     = hp0;
    *(__nv_bfloat162*)(d + 2048 + q * 4 + 2) = hp1;
}

__global__ void __launch_bounds__(256) prep_wsplit(
    const float* __restrict__ W0, const float* __restrict__ W1,
    const float* __restrict__ W2, const float* __restrict__ W3,
    __nv_bfloat16* __restrict__ dst)
{
    int t = blockIdx.x * 256 + threadIdx.x;
    int n = t / 768;
    int k4 = (t - n * 768) * 4;
    int band = k4 >> 10;
    int kk = k4 & 1023;
    int g = n >> 10, c = n & 1023;
    const float* W = (g == 0) ? W0 : (g == 1) ? W1 : (g == 2) ? W2 : W3;
    __nv_bfloat16 o[4];
    #pragma unroll
    for (int j = 0; j < 4; j++) {
        float w = __ldg(W + (size_t)(kk + j) * 1024 + c);
        __nv_bfloat16 h, l;
        split_bf(w, h, l);
        o[j] = (band < 2) ? h : l;
    }
    __nv_bfloat16* d = dst + (size_t)n * KCAT + k4;
    *(__nv_bfloat162*)(d)     = {o[0], o[1]};
    *(__nv_bfloat162*)(d + 2) = {o[2], o[3]};
}

__global__ void __launch_bounds__(256) prep_bias(
    const float* __restrict__ b0, const float* __restrict__ b1,
    const float* __restrict__ b2, const float* __restrict__ b3)
{
    int n = blockIdx.x * 256 + threadIdx.x;
    int g = n >> 10, c = n & 1023;
    const float* b = (g == 0) ? b0 : (g == 1) ? b1 : (g == 2) ? b2 : b3;
    g_bcat[n] = b[c];
}

__global__ void __launch_bounds__(256) prep_h0(const float* __restrict__ h0)
{
    int row = blockIdx.x;
    #pragma unroll
    for (int i = 0; i < 4; i++) {
        int k = i * 256 + threadIdx.x;
        float v = h0[row * 1024 + k];
        __nv_bfloat16 hi, lo;
        split_bf(v, hi, lo);
        g_h0cat[row * 2048 + k]        = hi;
        g_h0cat[row * 2048 + 1024 + k] = lo;
    }
}

// ============================================================
// grid barrier
// ============================================================
__device__ __forceinline__ void grid_sync_128(int tid)
{
    __syncthreads();
    if (tid == 0) {
        unsigned gen = *(volatile unsigned*)&g_bar_gen;
        __threadfence();
        if (atomicAdd(&g_bar_count, 1u) == NBLK - 1) {
            g_bar_count = 0;
            __threadfence();
            atomicExch(&g_bar_gen, gen + 1u);
        } else {
            while (*(volatile unsigned*)&g_bar_gen == gen) { __nanosleep(64); }
            __threadfence();
        }
    }
    __syncthreads();
}

// ============================================================
// Tensorized persistent LSTM recurrence (champion config).
// 128 blocks x 256 threads (8 warps). Block owns 8 hidden cols (32 gate-cols).
// U split hi/lo staged ONCE in smem (128 KB, SW128, ldmatrix layout).
// h streamed in 128-k chunks, 2-buffer cp.async. Warp tile 16m x 16n (2 gates);
// per 16-k: 4 ldsm4 + 6 HMMA. Gate recombine via smem exchange; cell state in
// registers; epilogue writes h as [hi|lo|hi] bands straight into g_hcat.
// smem: U 128K + h 2x32K = 192 KB.
// ============================================================
#define RSM_ULO 65536
#define RSM_H   131072
#define RSM_HBUF 32768
#define RSM_TOTAL 196608

extern "C" __global__ void __launch_bounds__(256, 1) lstm_mma(
    const float* __restrict__ Ui, const float* __restrict__ Uf,
    const float* __restrict__ Uj, const float* __restrict__ Uo,
    const float* __restrict__ c0)
{
    extern __shared__ char sm[];
    const uint32_t sb = smem_u32(sm);
    const int tid  = threadIdx.x;
    const int lane = tid & 31;
    const int w    = tid >> 5;
    const int wm   = (w & 3) * 16;   // batch rows wm..wm+15
    const int gh   = w >> 2;         // gate half: 0 -> {i,f}, 1 -> {j,o}
    const int n0   = blockIdx.x * 8;

    // ---- stage U hi/lo once: region layout [k64-chunk][nrow][64k] SW128 ----
    const float* Uptr[4] = {Ui, Uf, Uj, Uo};
    for (int it = 0; it < 128; it++) {
        int idx = it * 256 + tid;            // 0..32767 = (k, nrow)
        int k = idx >> 5, nrow = idx & 31;   // nrow = g*8 + c
        int g = nrow >> 3, c = nrow & 7;
        float v = __ldg(Uptr[g] + (size_t)k * 1024 + n0 + c);
        __nv_bfloat16 hi, lo;
        split_bf(v, hi, lo);
        uint32_t off = (k >> 6) * 4096 + SWZ128(nrow * 128 + (k & 63) * 2);
        *(__nv_bfloat16*)(sm + off)           = hi;
        *(__nv_bfloat16*)(sm + RSM_ULO + off) = lo;
    }

    // ---- cell-state ownership (fixed across steps) ----
    const int e_row = tid >> 2;              // batch row 0..63
    const int e_c2  = (tid & 3) * 2;         // 2 hidden cols
    float2 creg = *(const float2*)(c0 + e_row * H_ + n0 + e_c2);
    __syncthreads();

    // fragment lane addressing
    const int a_row = wm + (lane & 15);
    const int a_kb  = (lane >> 4) * 16;
    const int b_row = gh * 16 + ((lane >> 4) << 3) + (lane & 7);
    const int b_kb  = ((lane >> 3) & 1) * 16;
    const int er = lane >> 2;
    const int ec = (lane & 3) * 2;

    float* sgf = (float*)(sm + RSM_H);       // gate exchange [64][34] (reuses h buf0)

    for (int t = 0; t < T_; t++) {
        // h source for this step
        const __nv_bfloat16* hbase;
        size_t rstr;
        if (t == 0) { hbase = g_h0cat;                       rstr = 2048;  }
        else        { hbase = g_hcat + (size_t)(t - 1) * KCAT; rstr = 256 * (size_t)KCAT; }

        auto issue = [&](int bf, int cc) {
            uint32_t hb = sb + RSM_H + bf * RSM_HBUF;
            int kbase = cc * 128;
            #pragma unroll
            for (int i = 0; i < 8; i++) {
                int u = i * 256 + tid;
                int half = u >> 10, rem = u & 1023;
                int row = rem >> 4, seg = rem & 15;
                const __nv_bfloat16* src =
                    hbase + (size_t)row * rstr + half * 1024 + kbase + seg * 8;
                uint32_t dst = hb + half * 16384 + (seg >> 3) * 8192
                             + SWZ128(row * 128 + (seg & 7) * 16);
                cpasync16(dst, src);
            }
            CP_COMMIT();
        };

        // prefetch gx for this thread's 2 cells
        const float* gxp = g_gx + ((size_t)t * 64 + e_row) * G4 + n0 + e_c2;
        float2 gxi = *(const float2*)(gxp);
        float2 gxf = *(const float2*)(gxp + 1024);
        float2 gxj = *(const float2*)(gxp + 2048);
        float2 gxo = *(const float2*)(gxp + 3072);

        float acc[2][4];
        #pragma unroll
        for (int i = 0; i < 2; i++)
            #pragma unroll
            for (int q = 0; q < 4; q++) acc[i][q] = 0.f;

        issue(0, 0);

        for (int cc = 0; cc < 8; cc++) {
            if (cc < 7) { issue((cc + 1) & 1, cc + 1); CP_WAIT1(); }
            else        { CP_WAIT0(); }
            __syncthreads();

            uint32_t hb = sb + RSM_H + (cc & 1) * RSM_HBUF;
            #pragma unroll
            for (int ks = 0; ks < 8; ks++) {
                int sub = ks >> 2, ks4 = ks & 3;
                uint32_t a_off = sub * 8192 + SWZ128(a_row * 128 + ks4 * 32 + a_kb);
                uint32_t ahi[4], alo[4], bhi[4], blo[4];
                ldsm4(ahi, hb + a_off);
                ldsm4(alo, hb + 16384 + a_off);
                uint32_t b_off = (cc * 2 + sub) * 4096
                               + SWZ128(b_row * 128 + ks4 * 32 + b_kb);
                ldsm4(bhi, sb + b_off);
                ldsm4(blo, sb + RSM_ULO + b_off);
                mma16816(acc[0], ahi, &bhi[0]);
                mma16816(acc[1], ahi, &bhi[2]);
                mma16816(acc[0], alo, &bhi[0]);
                mma16816(acc[1], alo, &bhi[2]);
                mma16816(acc[0], ahi, &blo[0]);
                mma16816(acc[1], ahi, &blo[2]);
            }
            __syncthreads();
        }

        // ---- gate exchange (reuses h buf0 region; buf0 idle after chunk 6) ----
        #pragma unroll
        for (int nt = 0; nt < 2; nt++) {
            int g = gh * 2 + nt;
            sgf[(wm + er) * 34 + g * 8 + ec]         = acc[nt][0];
            sgf[(wm + er) * 34 + g * 8 + ec + 1]     = acc[nt][1];
            sgf[(wm + er + 8) * 34 + g * 8 + ec]     = acc[nt][2];
            sgf[(wm + er + 8) * 34 + g * 8 + ec + 1] = acc[nt][3];
        }
        __syncthreads();

        float2 pg[4];
        #pragma unroll
        for (int g = 0; g < 4; g++)
            pg[g] = *(const float2*)&sgf[e_row * 34 + g * 8 + e_c2];

        float2 hv;
        {
            float gi = pg[0].x + gxi.x, gf = pg[1].x + gxf.x;
            float gj = pg[2].x + gxj.x, go = pg[3].x + gxo.x;
            float iv = sigf(gi), fv = sigf(gf), jv = tanhfast(gj), ov = sigf(go);
            creg.x = fv * creg.x + iv * jv;
            hv.x = ov * tanhfast(creg.x);
        }
        {
            float gi = pg[0].y + gxi.y, gf = pg[1].y + gxf.y;
            float gj = pg[2].y + gxj.y, go = pg[3].y + gxo.y;
            float iv = sigf(gi), fv = sigf(gf), jv = tanhfast(gj), ov = sigf(go);
            creg.y = fv * creg.y + iv * jv;
            hv.y = ov * tanhfast(creg.y);
        }

        // write h split straight into g_hcat [hi | lo | hi] (y-GEMM layout)
        {
            __nv_bfloat16 hx, lx, hy, ly;
            split_bf(hv.x, hx, lx);
            split_bf(hv.y, hy, ly);
            __nv_bfloat16* d = g_hcat + ((size_t)e_row * 256 + t) * KCAT + n0 + e_c2;
            __nv_bfloat162 hp = {hx, hy}, lp = {lx, ly};
            *(__nv_bfloat162*)(d)        = hp;
            *(__nv_bfloat162*)(d + 1024) = lp;
            *(__nv_bfloat162*)(d + 2048) = hp;
        }

        grid_sync_128(tid);
    }
}

// ============================================================
// Inputs: x, h0, c0, W_i..W_o, U_i..U_o, b_i..b_o, W_y, b_y
// ============================================================
extern "C" void kernel_launch(void* const* d_in, const int* in_sizes, int n_in,
                              void* d_out, int out_size)
{
    const float* x  = (const float*)d_in[0];
    const float* h0 = (const float*)d_in[1];
    const float* c0 = (const float*)d_in[2];
    const float* W[4] = {(const float*)d_in[3], (const float*)d_in[4],
                         (const float*)d_in[5], (const float*)d_in[6]};
    const float* U[4] = {(const float*)d_in[7], (const float*)d_in[8],
                         (const float*)d_in[9], (const float*)d_in[10]};
    const float* bb[4] = {(const float*)d_in[11], (const float*)d_in[12],
                          (const float*)d_in[13], (const float*)d_in[14]};
    const float* Wy = (const float*)d_in[15];
    const float* by = (const float*)d_in[16];
    float* y = (float*)d_out;

    float* gx_ptr; cudaGetSymbolAddress((void**)&gx_ptr, g_gx);
    __nv_bfloat16* acat; cudaGetSymbolAddress((void**)&acat, g_acat);
    __nv_bfloat16* hcat; cudaGetSymbolAddress((void**)&hcat, g_hcat);
    __nv_bfloat16* bgx;  cudaGetSymbolAddress((void**)&bgx,  g_bgx);
    __nv_bfloat16* bwy;  cudaGetSymbolAddress((void**)&bwy,  g_bwy);
    float* bcat; cudaGetSymbolAddress((void**)&bcat, g_bcat);

    const int gemm_smem = 65536;
    cudaFuncSetAttribute(gemm_mma<true>,
                         cudaFuncAttributeMaxDynamicSharedMemorySize, gemm_smem);
    cudaFuncSetAttribute(gemm_mma<false>,
                         cudaFuncAttributeMaxDynamicSharedMemorySize, gemm_smem);
    cudaFuncSetAttribute(lstm_mma,
                         cudaFuncAttributeMaxDynamicSharedMemorySize, RSM_TOTAL);

    // prep
    prep_split<<<16384, 256>>>(x, acat);
    prep_wsplit<<<12288, 256>>>(W[0], W[1], W[2], W[3], bgx);
    prep_wsplit<<<3072, 256>>>(Wy, Wy, Wy, Wy, bwy);
    prep_bias<<<16, 256>>>(bb[0], bb[1], bb[2], bb[3]);
    prep_h0<<<64, 256>>>(h0);

    // gx = x @ [W_i|W_f|W_j|W_o] + b  (REMAP into [T][B][4H])
    gemm_mma<true><<<dim3(G4 / 128, 16384 / 128), 256, gemm_smem>>>(
        acat, bgx, bcat, gx_ptr, G4);

    // tensorized persistent recurrence (writes g_hcat directly)
    lstm_mma<<<NBLK, 256, RSM_TOTAL>>>(U[0], U[1], U[2], U[3], c0);

    // y = hs @ W_y + b_y
    gemm_mma<false><<<dim3(1024 / 128, 16384 / 128), 256, gemm_smem>>>(
        hcat, bwy, by, y, 1024);
}